// round 3
// baseline (speedup 1.0000x reference)
#include <cuda_runtime.h>
#include <cstdint>

#define NB   150
#define NA   3
#define NC   80
#define BATCH 8
#define EPSF 1e-6f
#define NTHREADS 256

// 3 global accumulators: giou, conf, cls (double for deterministic-enough reduction)
__device__ double g_acc[3];

__global__ void zero_acc_kernel() {
    if (threadIdx.x < 3) g_acc[threadIdx.x] = 0.0;
}

__device__ __forceinline__ float softplus_f(float x) {
    // max(x,0) + log(1 + exp(-|x|)) , fast-math variants
    return fmaxf(x, 0.0f) + __logf(1.0f + __expf(-fabsf(x)));
}

__global__ __launch_bounds__(NTHREADS)
void layer_loss_kernel(const float* __restrict__ p,
                       const float* __restrict__ pd,
                       const float* __restrict__ lab,
                       const float* __restrict__ boxes,
                       int g)
{
    __shared__ float bx1[NB], by1[NB], bx2[NB], by2[NB], bar[NB];

    const int b   = blockIdx.y;
    const int tid = threadIdx.x;

    // Preprocess this batch's 150 boxes into xyxy + area (shared, broadcast-read later)
    for (int i = tid; i < NB; i += NTHREADS) {
        const float* bb = boxes + ((size_t)b * NB + i) * 4;
        float x = bb[0], y = bb[1], w = bb[2], h = bb[3];
        bx1[i] = x - 0.5f * w;
        by1[i] = y - 0.5f * h;
        bx2[i] = x + 0.5f * w;
        by2[i] = y + 0.5f * h;
        bar[i] = w * h;
    }
    __syncthreads();

    const int gga = g * g * NA;
    const int j   = blockIdx.x * NTHREADS + tid;

    float lg = 0.0f, lc = 0.0f, lk = 0.0f;

    if (j < gga) {
        const size_t base = (size_t)b * gga + j;
        const float* L  = lab + base * 86;
        const float* PD = pd  + base * 85;
        const float* P  = p   + base * 85;

        const float obj = L[4];
        const float mix = L[5];

        const float pcx = PD[0], pcy = PD[1], pw = PD[2], ph = PD[3];
        const float px1 = pcx - 0.5f * pw, px2 = pcx + 0.5f * pw;
        const float py1 = pcy - 0.5f * ph, py2 = pcy + 0.5f * ph;
        const float a1  = pw * ph;

        const float pconf = P[4];

        // focal-conf pieces (needed for every anchor)
        const float sig = 1.0f / (1.0f + __expf(-pconf));
        const float bce = softplus_f(pconf) - pconf * obj;
        const float dft = obj - sig;
        const float fl  = bce * dft * dft;   // gamma=2, alpha=1

        float coef;
        if (obj > 0.0f) {
            coef = obj;  // noobj term is zero when obj==1

            // ---- GIoU vs label box ----
            const float lx = L[0], ly = L[1], lw = L[2], lh = L[3];
            const float lx1 = lx - 0.5f * lw, lx2 = lx + 0.5f * lw;
            const float ly1 = ly - 0.5f * lh, ly2 = ly + 0.5f * lh;
            const float a2  = lw * lh;

            float iw = fminf(px2, lx2) - fmaxf(px1, lx1);
            float ih = fminf(py2, ly2) - fmaxf(py1, ly1);
            iw = fmaxf(iw, 0.0f);
            ih = fmaxf(ih, 0.0f);
            const float inter = iw * ih;
            const float uni   = a1 + a2 - inter;
            const float iou   = inter / fmaxf(uni, EPSF);

            float ew = fmaxf(px2, lx2) - fminf(px1, lx1);
            float eh = fmaxf(py2, ly2) - fminf(py1, ly1);
            ew = fmaxf(ew, 0.0f);
            eh = fmaxf(eh, 0.0f);
            const float ea   = ew * eh;
            const float giou = iou - (ea - uni) / fmaxf(ea, EPSF);

            lg = obj * (1.0f - giou) * mix;

            // ---- class BCE (only when obj != 0) ----
            float s = 0.0f;
            #pragma unroll 4
            for (int c = 0; c < NC; c++) {
                const float x = P[5 + c];
                const float t = L[6 + c];
                s += softplus_f(x) - x * t;
            }
            lk = obj * s * mix;
        } else {
            // ---- noobj: is max IoU over 150 boxes >= 0.5 ?  (division-free) ----
            bool hit = false;
            #pragma unroll 5
            for (int i = 0; i < NB; i++) {
                float iw = fminf(px2, bx2[i]) - fmaxf(px1, bx1[i]);
                float ih = fminf(py2, by2[i]) - fmaxf(py1, by1[i]);
                iw = fmaxf(iw, 0.0f);
                ih = fmaxf(ih, 0.0f);
                const float inter = iw * ih;
                const float u = fmaxf(a1 + bar[i] - inter, EPSF);
                hit = hit || (inter >= 0.5f * u);   // inter/u >= 0.5
            }
            coef = hit ? 0.0f : 1.0f;   // (1-obj) * (iou_max < 0.5)
        }
        lc = coef * fl * mix;
    }

    // ---- block reduction: warp shuffle, then cross-warp via shared ----
    #pragma unroll
    for (int o = 16; o > 0; o >>= 1) {
        lg += __shfl_down_sync(0xFFFFFFFFu, lg, o);
        lc += __shfl_down_sync(0xFFFFFFFFu, lc, o);
        lk += __shfl_down_sync(0xFFFFFFFFu, lk, o);
    }
    __shared__ float rg[NTHREADS / 32], rc[NTHREADS / 32], rk[NTHREADS / 32];
    const int w = tid >> 5, l = tid & 31;
    if (l == 0) { rg[w] = lg; rc[w] = lc; rk[w] = lk; }
    __syncthreads();
    if (tid == 0) {
        float sg = 0.0f, sc = 0.0f, sk = 0.0f;
        #pragma unroll
        for (int i = 0; i < NTHREADS / 32; i++) { sg += rg[i]; sc += rc[i]; sk += rk[i]; }
        atomicAdd(&g_acc[0], (double)sg);
        atomicAdd(&g_acc[1], (double)sc);
        atomicAdd(&g_acc[2], (double)sk);
    }
}

__global__ void finalize_kernel(float* __restrict__ out) {
    if (threadIdx.x == 0) {
        const float lg = (float)(g_acc[0] / (double)BATCH);
        const float lc = (float)(g_acc[1] / (double)BATCH);
        const float lk = (float)(g_acc[2] / (double)BATCH);
        out[0] = lg + lc + lk;
        out[1] = lg;
        out[2] = lc;
        out[3] = lk;
    }
}

extern "C" void kernel_launch(void* const* d_in, const int* in_sizes, int n_in,
                              void* d_out, int out_size)
{
    // ACTUAL harness order = dict insertion order of setup_inputs():
    //   per scale i in {s,m,l}:  p_i, p_d_i, label_i   (interleaved!)
    //   then sbboxes, mbboxes, lbboxes
    // 0: p_s       1: p_d_s   2: label_sbbox
    // 3: p_m       4: p_d_m   5: label_mbbox
    // 6: p_l       7: p_d_l   8: label_lbbox
    // 9: sbboxes  10: mbboxes 11: lbboxes
    const float* p[3]   = { (const float*)d_in[0], (const float*)d_in[3], (const float*)d_in[6] };
    const float* pd[3]  = { (const float*)d_in[1], (const float*)d_in[4], (const float*)d_in[7] };
    const float* lab[3] = { (const float*)d_in[2], (const float*)d_in[5], (const float*)d_in[8] };
    const float* bx[3]  = { (const float*)d_in[9], (const float*)d_in[10], (const float*)d_in[11] };
    const int grids[3] = { 76, 38, 19 };

    float* out = (float*)d_out;

    zero_acc_kernel<<<1, 32>>>();
    for (int s = 0; s < 3; s++) {
        const int g   = grids[s];
        const int gga = g * g * NA;
        dim3 grid((gga + NTHREADS - 1) / NTHREADS, BATCH);
        layer_loss_kernel<<<grid, NTHREADS>>>(p[s], pd[s], lab[s], bx[s], g);
    }
    finalize_kernel<<<1, 32>>>(out);
}

// round 4
// speedup vs baseline: 1.7755x; 1.7755x over previous
#include <cuda_runtime.h>
#include <cstdint>

#define NB    150
#define NC    80
#define BATCH 8
#define EPSF  1e-6f
#define NT    256          // threads per block
#define APT   2            // anchors per thread
#define APB   (NT*APT)     // 512 anchors per block

// anchors per batch, per scale
#define N_S 17328          // 76*76*3
#define N_M 4332           // 38*38*3
#define N_L 1083           // 19*19*3
#define B_S 34             // ceil(N_S/APB)
#define B_M 9              // ceil(N_M/APB)
#define B_L 3              // ceil(N_L/APB)
#define BPB (B_S+B_M+B_L)  // 46 blocks per batch
#define GRID (BPB*BATCH)   // 368

__device__ double g_acc[3];

__global__ void zero_acc_kernel() {
    if (threadIdx.x < 3) g_acc[threadIdx.x] = 0.0;
}

__device__ __forceinline__ float softplus_f(float x) {
    return fmaxf(x, 0.0f) + __logf(1.0f + __expf(-fabsf(x)));
}

__global__ __launch_bounds__(NT)
void fused_loss_kernel(const float* __restrict__ p0,  const float* __restrict__ pd0, const float* __restrict__ l0,
                       const float* __restrict__ p1,  const float* __restrict__ pd1, const float* __restrict__ l1,
                       const float* __restrict__ p2,  const float* __restrict__ pd2, const float* __restrict__ l2,
                       const float* __restrict__ b0,  const float* __restrict__ b1, const float* __restrict__ b2)
{
    const int tid   = threadIdx.x;
    const int bid   = blockIdx.x;
    const int batch = bid / BPB;
    const int r     = bid % BPB;

    const float *P, *PD, *L, *BX;
    int n, blk;
    if (r < B_S)            { P = p0; PD = pd0; L = l0; BX = b0; n = N_S; blk = r; }
    else if (r < B_S + B_M) { P = p1; PD = pd1; L = l1; BX = b1; n = N_M; blk = r - B_S; }
    else                    { P = p2; PD = pd2; L = l2; BX = b2; n = N_L; blk = r - B_S - B_M; }

    // ---- batch boxes -> shared as (x1,y1,x2,y2); area recomputed from corners ----
    __shared__ float4 sb[NB];
    for (int i = tid; i < NB; i += NT) {
        float4 v = reinterpret_cast<const float4*>(BX)[batch * NB + i];
        float4 c;
        c.x = v.x - 0.5f * v.z;  c.y = v.y - 0.5f * v.w;
        c.z = v.x + 0.5f * v.z;  c.w = v.y + 0.5f * v.w;
        sb[i] = c;
    }
    __syncthreads();

    // ---- per-thread: two anchors, headers ----
    float px1[APT], py1[APT], px2[APT], py2[APT], a1[APT], pconf[APT], obj[APT], mix[APT];
    int   base[APT];  bool valid[APT];

    const int j0 = blk * APB + tid;
    #pragma unroll
    for (int a = 0; a < APT; a++) {
        const int j = j0 + a * NT;
        valid[a] = (j < n);
        base[a]  = batch * n + j;
        if (valid[a]) {
            const float* PDp = PD + (size_t)base[a] * 85;
            const float pcx = PDp[0], pcy = PDp[1], pw = PDp[2], ph = PDp[3];
            px1[a] = pcx - 0.5f * pw;  px2[a] = pcx + 0.5f * pw;
            py1[a] = pcy - 0.5f * ph;  py2[a] = pcy + 0.5f * ph;
            a1[a]  = pw * ph;
            pconf[a] = P[(size_t)base[a] * 85 + 4];
            const float2 om = *reinterpret_cast<const float2*>(L + (size_t)base[a] * 86 + 4); // 8B-aligned
            obj[a] = om.x;  mix[a] = om.y;
        } else {
            px1[a]=px2[a]=py1[a]=py2[a]=a1[a]=pconf[a]=obj[a]=mix[a]=0.0f;
        }
    }

    // ---- hot loop: uniform for all lanes, both anchors share one LDS.128 ----
    // iou >= 0.5  <=>  3*inter >= a1 + barea   (union >= 1 here, EPS clamp never binds)
    float m0 = -1e30f, m1 = -1e30f;
    #pragma unroll 2
    for (int i = 0; i < NB; i++) {
        const float4 bb = sb[i];
        const float barea = (bb.z - bb.x) * (bb.w - bb.y);
        {
            float iw = fminf(px2[0], bb.z) - fmaxf(px1[0], bb.x);
            float ih = fminf(py2[0], bb.w) - fmaxf(py1[0], bb.y);
            iw = fmaxf(iw, 0.0f);  ih = fmaxf(ih, 0.0f);
            m0 = fmaxf(m0, fmaf(3.0f, iw * ih, -(a1[0] + barea)));
        }
        {
            float iw = fminf(px2[1], bb.z) - fmaxf(px1[1], bb.x);
            float ih = fminf(py2[1], bb.w) - fmaxf(py1[1], bb.y);
            iw = fmaxf(iw, 0.0f);  ih = fmaxf(ih, 0.0f);
            m1 = fmaxf(m1, fmaf(3.0f, iw * ih, -(a1[1] + barea)));
        }
    }

    float lg = 0.0f, lc = 0.0f, lk = 0.0f;
    float objmix[APT];

    #pragma unroll
    for (int a = 0; a < APT; a++) {
        const float x   = pconf[a];
        const float sig = 1.0f / (1.0f + __expf(-x));
        const float bce = softplus_f(x) - x * obj[a];
        const float d   = obj[a] - sig;
        const float fl  = bce * d * d;

        float coef;
        if (obj[a] > 0.0f) {
            coef = obj[a];
            // ---- GIoU vs label box (rare path) ----
            const float2 lxy = *reinterpret_cast<const float2*>(L + (size_t)base[a] * 86);     // 8B-aligned
            const float2 lwh = *reinterpret_cast<const float2*>(L + (size_t)base[a] * 86 + 2); // 8B-aligned
            const float lx1 = lxy.x - 0.5f * lwh.x, lx2 = lxy.x + 0.5f * lwh.x;
            const float ly1 = lxy.y - 0.5f * lwh.y, ly2 = lxy.y + 0.5f * lwh.y;
            const float a2  = lwh.x * lwh.y;

            float iw = fminf(px2[a], lx2) - fmaxf(px1[a], lx1);
            float ih = fminf(py2[a], ly2) - fmaxf(py1[a], ly1);
            iw = fmaxf(iw, 0.0f);  ih = fmaxf(ih, 0.0f);
            const float inter = iw * ih;
            const float uni   = a1[a] + a2 - inter;
            const float iou   = inter / fmaxf(uni, EPSF);

            float ew = fmaxf(px2[a], lx2) - fminf(px1[a], lx1);
            float eh = fmaxf(py2[a], ly2) - fminf(py1[a], ly1);
            ew = fmaxf(ew, 0.0f);  eh = fmaxf(eh, 0.0f);
            const float ea   = ew * eh;
            const float giou = iou - (ea - uni) / fmaxf(ea, EPSF);

            lg += obj[a] * (1.0f - giou) * mix[a];
        } else {
            const float m = (a == 0) ? m0 : m1;
            coef = (m >= 0.0f) ? 0.0f : 1.0f;
        }
        lc += coef * fl * mix[a];            // mix=0 for invalid anchors -> 0
        objmix[a] = (valid[a] && obj[a] > 0.0f) ? obj[a] * mix[a] : 0.0f;
    }

    // ---- cooperative class-BCE: whole warp serves each obj anchor ----
    const int lane = tid & 31;
    #pragma unroll
    for (int a = 0; a < APT; a++) {
        unsigned mask = __ballot_sync(0xFFFFFFFFu, objmix[a] > 0.0f);
        while (mask) {
            const int src = __ffs(mask) - 1;
            mask &= mask - 1;
            const int   sbase = __shfl_sync(0xFFFFFFFFu, base[a], src);
            const float w     = __shfl_sync(0xFFFFFFFFu, objmix[a], src);
            const float* Pc = P + (size_t)sbase * 85 + 5;
            const float* Lc = L + (size_t)sbase * 86 + 6;
            float s = 0.0f;
            #pragma unroll
            for (int c = lane; c < NC; c += 32) {
                const float xx = Pc[c];
                s += softplus_f(xx) - xx * Lc[c];
            }
            #pragma unroll
            for (int o = 16; o > 0; o >>= 1) s += __shfl_down_sync(0xFFFFFFFFu, s, o);
            if (lane == 0) lk += w * s;
        }
    }

    // ---- block reduction ----
    #pragma unroll
    for (int o = 16; o > 0; o >>= 1) {
        lg += __shfl_down_sync(0xFFFFFFFFu, lg, o);
        lc += __shfl_down_sync(0xFFFFFFFFu, lc, o);
        lk += __shfl_down_sync(0xFFFFFFFFu, lk, o);
    }
    __shared__ float rg[NT/32], rc[NT/32], rk[NT/32];
    const int w = tid >> 5;
    if (lane == 0) { rg[w] = lg; rc[w] = lc; rk[w] = lk; }
    __syncthreads();
    if (tid == 0) {
        float sg = 0.0f, sc = 0.0f, sk = 0.0f;
        #pragma unroll
        for (int i = 0; i < NT/32; i++) { sg += rg[i]; sc += rc[i]; sk += rk[i]; }
        atomicAdd(&g_acc[0], (double)sg);
        atomicAdd(&g_acc[1], (double)sc);
        atomicAdd(&g_acc[2], (double)sk);
    }
}

__global__ void finalize_kernel(float* __restrict__ out) {
    if (threadIdx.x == 0) {
        const float lg = (float)(g_acc[0] / (double)BATCH);
        const float lc = (float)(g_acc[1] / (double)BATCH);
        const float lk = (float)(g_acc[2] / (double)BATCH);
        out[0] = lg + lc + lk;
        out[1] = lg;
        out[2] = lc;
        out[3] = lk;
    }
}

extern "C" void kernel_launch(void* const* d_in, const int* in_sizes, int n_in,
                              void* d_out, int out_size)
{
    // harness order = dict insertion order of setup_inputs() (interleaved per scale):
    // 0: p_s   1: p_d_s  2: label_sbbox
    // 3: p_m   4: p_d_m  5: label_mbbox
    // 6: p_l   7: p_d_l  8: label_lbbox
    // 9: sbboxes  10: mbboxes  11: lbboxes
    const float* p0  = (const float*)d_in[0];
    const float* pd0 = (const float*)d_in[1];
    const float* l0  = (const float*)d_in[2];
    const float* p1  = (const float*)d_in[3];
    const float* pd1 = (const float*)d_in[4];
    const float* l1  = (const float*)d_in[5];
    const float* p2  = (const float*)d_in[6];
    const float* pd2 = (const float*)d_in[7];
    const float* l2  = (const float*)d_in[8];
    const float* b0  = (const float*)d_in[9];
    const float* b1  = (const float*)d_in[10];
    const float* b2  = (const float*)d_in[11];

    float* out = (float*)d_out;

    zero_acc_kernel<<<1, 32>>>();
    fused_loss_kernel<<<GRID, NT>>>(p0, pd0, l0, p1, pd1, l1, p2, pd2, l2, b0, b1, b2);
    finalize_kernel<<<1, 32>>>(out);
}

// round 5
// speedup vs baseline: 1.8106x; 1.0198x over previous
#include <cuda_runtime.h>
#include <cstdint>

#define NB    150
#define NC    80
#define BATCH 8
#define EPSF  1e-6f
#define NT    256          // threads per block
#define APT   2            // anchors per thread
#define APB   (NT*APT)     // 512 anchors per block

// anchors per batch, per scale
#define N_S 17328          // 76*76*3
#define N_M 4332           // 38*38*3
#define N_L 1083           // 19*19*3
#define B_S 34             // ceil(N_S/APB)
#define B_M 9              // ceil(N_M/APB)
#define B_L 3              // ceil(N_L/APB)
#define BPB (B_S+B_M+B_L)  // 46 blocks per batch
#define GRID (BPB*BATCH)   // 368

// per-block partials (always fully written each run -> no zeroing kernel needed)
__device__ double g_pg[GRID];
__device__ double g_pc[GRID];
__device__ double g_pk[GRID];
__device__ unsigned g_count = 0;   // reset to 0 by the finishing block each run

__device__ __forceinline__ float softplus_f(float x) {
    return fmaxf(x, 0.0f) + __logf(1.0f + __expf(-fabsf(x)));
}

__global__ __launch_bounds__(NT)
void fused_loss_kernel(const float* __restrict__ p0,  const float* __restrict__ pd0, const float* __restrict__ l0,
                       const float* __restrict__ p1,  const float* __restrict__ pd1, const float* __restrict__ l1,
                       const float* __restrict__ p2,  const float* __restrict__ pd2, const float* __restrict__ l2,
                       const float* __restrict__ b0,  const float* __restrict__ b1,  const float* __restrict__ b2,
                       float* __restrict__ out)
{
    const int tid   = threadIdx.x;
    const int bid   = blockIdx.x;
    const int batch = bid / BPB;
    const int r     = bid % BPB;

    const float *P, *PD, *L, *BX;
    int n, blk;
    if (r < B_S)            { P = p0; PD = pd0; L = l0; BX = b0; n = N_S; blk = r; }
    else if (r < B_S + B_M) { P = p1; PD = pd1; L = l1; BX = b1; n = N_M; blk = r - B_S; }
    else                    { P = p2; PD = pd2; L = l2; BX = b2; n = N_L; blk = r - B_S - B_M; }

    // ---- batch boxes -> shared as (x1,y1,x2,y2) ----
    __shared__ float4 sb[NB];
    for (int i = tid; i < NB; i += NT) {
        float4 v = reinterpret_cast<const float4*>(BX)[batch * NB + i];
        float4 c;
        c.x = v.x - 0.5f * v.z;  c.y = v.y - 0.5f * v.w;
        c.z = v.x + 0.5f * v.z;  c.w = v.y + 0.5f * v.w;
        sb[i] = c;
    }
    __syncthreads();

    // ---- per-thread: two anchors, headers ----
    float px1[APT], py1[APT], px2[APT], py2[APT], a1[APT], pconf[APT], obj[APT], mix[APT];
    int   base[APT];  bool valid[APT];

    const int j0 = blk * APB + tid;
    #pragma unroll
    for (int a = 0; a < APT; a++) {
        const int j = j0 + a * NT;
        valid[a] = (j < n);
        base[a]  = batch * n + j;
        if (valid[a]) {
            const float* PDp = PD + (size_t)base[a] * 85;
            const float pcx = PDp[0], pcy = PDp[1], pw = PDp[2], ph = PDp[3];
            px1[a] = pcx - 0.5f * pw;  px2[a] = pcx + 0.5f * pw;
            py1[a] = pcy - 0.5f * ph;  py2[a] = pcy + 0.5f * ph;
            a1[a]  = pw * ph;
            pconf[a] = P[(size_t)base[a] * 85 + 4];
            const float2 om = *reinterpret_cast<const float2*>(L + (size_t)base[a] * 86 + 4); // 8B-aligned
            obj[a] = om.x;  mix[a] = om.y;
        } else {
            px1[a]=px2[a]=py1[a]=py2[a]=a1[a]=pconf[a]=obj[a]=mix[a]=0.0f;
        }
    }

    // ---- hot loop: uniform for all lanes, both anchors share one LDS.128 ----
    // iou >= 0.5  <=>  3*inter >= a1 + barea   (w,h >= 1 so union >= 1; EPS clamp never binds)
    float m0 = -1e30f, m1 = -1e30f;
    #pragma unroll 2
    for (int i = 0; i < NB; i++) {
        const float4 bb = sb[i];
        const float barea = (bb.z - bb.x) * (bb.w - bb.y);
        {
            float iw = fminf(px2[0], bb.z) - fmaxf(px1[0], bb.x);
            float ih = fminf(py2[0], bb.w) - fmaxf(py1[0], bb.y);
            iw = fmaxf(iw, 0.0f);  ih = fmaxf(ih, 0.0f);
            m0 = fmaxf(m0, fmaf(3.0f, iw * ih, -(a1[0] + barea)));
        }
        {
            float iw = fminf(px2[1], bb.z) - fmaxf(px1[1], bb.x);
            float ih = fminf(py2[1], bb.w) - fmaxf(py1[1], bb.y);
            iw = fmaxf(iw, 0.0f);  ih = fmaxf(ih, 0.0f);
            m1 = fmaxf(m1, fmaf(3.0f, iw * ih, -(a1[1] + barea)));
        }
    }

    float lg = 0.0f, lc = 0.0f, lk = 0.0f;
    float objmix[APT];

    #pragma unroll
    for (int a = 0; a < APT; a++) {
        const float x   = pconf[a];
        const float sig = 1.0f / (1.0f + __expf(-x));
        const float bce = softplus_f(x) - x * obj[a];
        const float d   = obj[a] - sig;
        const float fl  = bce * d * d;

        float coef;
        if (obj[a] > 0.0f) {
            coef = obj[a];
            // ---- GIoU vs label box (rare path) ----
            const float2 lxy = *reinterpret_cast<const float2*>(L + (size_t)base[a] * 86);
            const float2 lwh = *reinterpret_cast<const float2*>(L + (size_t)base[a] * 86 + 2);
            const float lx1 = lxy.x - 0.5f * lwh.x, lx2 = lxy.x + 0.5f * lwh.x;
            const float ly1 = lxy.y - 0.5f * lwh.y, ly2 = lxy.y + 0.5f * lwh.y;
            const float a2  = lwh.x * lwh.y;

            float iw = fminf(px2[a], lx2) - fmaxf(px1[a], lx1);
            float ih = fminf(py2[a], ly2) - fmaxf(py1[a], ly1);
            iw = fmaxf(iw, 0.0f);  ih = fmaxf(ih, 0.0f);
            const float inter = iw * ih;
            const float uni   = a1[a] + a2 - inter;
            const float iou   = inter / fmaxf(uni, EPSF);

            float ew = fmaxf(px2[a], lx2) - fminf(px1[a], lx1);
            float eh = fmaxf(py2[a], ly2) - fminf(py1[a], ly1);
            ew = fmaxf(ew, 0.0f);  eh = fmaxf(eh, 0.0f);
            const float ea   = ew * eh;
            const float giou = iou - (ea - uni) / fmaxf(ea, EPSF);

            lg += obj[a] * (1.0f - giou) * mix[a];
        } else {
            const float m = (a == 0) ? m0 : m1;
            coef = (m >= 0.0f) ? 0.0f : 1.0f;
        }
        lc += coef * fl * mix[a];
        objmix[a] = (valid[a] && obj[a] > 0.0f) ? obj[a] * mix[a] : 0.0f;
    }

    // ---- cooperative class-BCE: whole warp serves each obj anchor ----
    const int lane = tid & 31;
    #pragma unroll
    for (int a = 0; a < APT; a++) {
        unsigned mask = __ballot_sync(0xFFFFFFFFu, objmix[a] > 0.0f);
        while (mask) {
            const int src = __ffs(mask) - 1;
            mask &= mask - 1;
            const int   sbase = __shfl_sync(0xFFFFFFFFu, base[a], src);
            const float w     = __shfl_sync(0xFFFFFFFFu, objmix[a], src);
            const float* Pc = P + (size_t)sbase * 85 + 5;
            const float* Lc = L + (size_t)sbase * 86 + 6;
            float s = 0.0f;
            #pragma unroll
            for (int c = lane; c < NC; c += 32) {
                const float xx = Pc[c];
                s += softplus_f(xx) - xx * Lc[c];
            }
            #pragma unroll
            for (int o = 16; o > 0; o >>= 1) s += __shfl_down_sync(0xFFFFFFFFu, s, o);
            if (lane == 0) lk += w * s;
        }
    }

    // ---- block reduction ----
    #pragma unroll
    for (int o = 16; o > 0; o >>= 1) {
        lg += __shfl_down_sync(0xFFFFFFFFu, lg, o);
        lc += __shfl_down_sync(0xFFFFFFFFu, lc, o);
        lk += __shfl_down_sync(0xFFFFFFFFu, lk, o);
    }
    __shared__ float rg[NT/32], rc[NT/32], rk[NT/32];
    __shared__ bool s_last;
    const int w = tid >> 5;
    if (lane == 0) { rg[w] = lg; rc[w] = lc; rk[w] = lk; }
    __syncthreads();

    if (tid == 0) {
        float sg = 0.0f, sc = 0.0f, sk = 0.0f;
        #pragma unroll
        for (int i = 0; i < NT/32; i++) { sg += rg[i]; sc += rc[i]; sk += rk[i]; }
        g_pg[bid] = (double)sg;
        g_pc[bid] = (double)sc;
        g_pk[bid] = (double)sk;
        __threadfence();
        const unsigned prev = atomicAdd(&g_count, 1u);
        s_last = (prev == GRID - 1);
    }
    __syncthreads();

    // ---- last block: reduce all partials, write outputs, reset counter ----
    if (s_last) {
        double dg = 0.0, dc = 0.0, dk = 0.0;
        for (int i = tid; i < GRID; i += NT) {
            dg += g_pg[i];  dc += g_pc[i];  dk += g_pk[i];
        }
        #pragma unroll
        for (int o = 16; o > 0; o >>= 1) {
            dg += __shfl_down_sync(0xFFFFFFFFu, dg, o);
            dc += __shfl_down_sync(0xFFFFFFFFu, dc, o);
            dk += __shfl_down_sync(0xFFFFFFFFu, dk, o);
        }
        __shared__ double zg[NT/32], zc[NT/32], zk[NT/32];
        if (lane == 0) { zg[w] = dg; zc[w] = dc; zk[w] = dk; }
        __syncthreads();
        if (tid == 0) {
            double fg = 0.0, fc = 0.0, fk = 0.0;
            #pragma unroll
            for (int i = 0; i < NT/32; i++) { fg += zg[i]; fc += zc[i]; fk += zk[i]; }
            const float og = (float)(fg / (double)BATCH);
            const float oc = (float)(fc / (double)BATCH);
            const float ok = (float)(fk / (double)BATCH);
            out[0] = og + oc + ok;
            out[1] = og;
            out[2] = oc;
            out[3] = ok;
            g_count = 0;           // restore state for next graph replay
        }
    }
}

extern "C" void kernel_launch(void* const* d_in, const int* in_sizes, int n_in,
                              void* d_out, int out_size)
{
    // harness order = dict insertion order of setup_inputs() (interleaved per scale):
    // 0: p_s   1: p_d_s  2: label_sbbox
    // 3: p_m   4: p_d_m  5: label_mbbox
    // 6: p_l   7: p_d_l  8: label_lbbox
    // 9: sbboxes  10: mbboxes  11: lbboxes
    fused_loss_kernel<<<GRID, NT>>>(
        (const float*)d_in[0], (const float*)d_in[1], (const float*)d_in[2],
        (const float*)d_in[3], (const float*)d_in[4], (const float*)d_in[5],
        (const float*)d_in[6], (const float*)d_in[7], (const float*)d_in[8],
        (const float*)d_in[9], (const float*)d_in[10], (const float*)d_in[11],
        (float*)d_out);
}

// round 6
// speedup vs baseline: 2.0888x; 1.1537x over previous
#include <cuda_runtime.h>
#include <cstdint>

#define NB    150
#define NC    80
#define BATCH 8
#define EPSF  1e-6f
#define NT    256          // threads per block, 1 anchor per thread

// anchors per batch, per scale
#define N_S 17328          // 76*76*3
#define N_M 4332           // 38*38*3
#define N_L 1083           // 19*19*3
#define B_S 68             // ceil(N_S/NT)
#define B_M 17             // ceil(N_M/NT)
#define B_L 5              // ceil(N_L/NT)
#define BPB (B_S+B_M+B_L)  // 90 blocks per batch
#define GRID (BPB*BATCH)   // 720

// per-block partials (always fully written each run -> no zeroing needed)
__device__ double g_pg[GRID];
__device__ double g_pc[GRID];
__device__ double g_pk[GRID];
__device__ unsigned g_count = 0;   // reset by finishing block each run

__device__ __forceinline__ float softplus_f(float x) {
    return fmaxf(x, 0.0f) + __logf(1.0f + __expf(-fabsf(x)));
}

__global__ __launch_bounds__(NT)
void fused_loss_kernel(const float* __restrict__ p0,  const float* __restrict__ pd0, const float* __restrict__ l0,
                       const float* __restrict__ p1,  const float* __restrict__ pd1, const float* __restrict__ l1,
                       const float* __restrict__ p2,  const float* __restrict__ pd2, const float* __restrict__ l2,
                       const float* __restrict__ b0,  const float* __restrict__ b1,  const float* __restrict__ b2,
                       float* __restrict__ out)
{
    const int tid   = threadIdx.x;
    const int bid   = blockIdx.x;
    const int batch = bid / BPB;
    const int r     = bid % BPB;

    const float *P, *PD, *L, *BX;
    int n, blk;
    if (r < B_S)            { P = p0; PD = pd0; L = l0; BX = b0; n = N_S; blk = r; }
    else if (r < B_S + B_M) { P = p1; PD = pd1; L = l1; BX = b1; n = N_M; blk = r - B_S; }
    else                    { P = p2; PD = pd2; L = l2; BX = b2; n = N_L; blk = r - B_S - B_M; }

    // ---- batch boxes -> shared as (x1,y1,x2,y2) + negated area ----
    __shared__ float4 sb[NB];
    __shared__ float  snb[NB];     // -(w*h)
    for (int i = tid; i < NB; i += NT) {
        float4 v = reinterpret_cast<const float4*>(BX)[batch * NB + i];
        float4 c;
        c.x = v.x - 0.5f * v.z;  c.y = v.y - 0.5f * v.w;
        c.z = v.x + 0.5f * v.z;  c.w = v.y + 0.5f * v.w;
        sb[i]  = c;
        snb[i] = -(v.z * v.w);
    }
    __syncthreads();

    // ---- this thread's anchor header ----
    const int j     = blk * NT + tid;
    const bool valid = (j < n);
    const int base  = batch * n + j;

    float px1 = 0.f, py1 = 0.f, px2 = 0.f, py2 = 0.f, a1 = 0.f;
    float pconf = 0.f, obj = 0.f, mix = 0.f;
    if (valid) {
        const float* PDp = PD + (size_t)base * 85;
        const float pcx = PDp[0], pcy = PDp[1], pw = PDp[2], ph = PDp[3];
        px1 = pcx - 0.5f * pw;  px2 = pcx + 0.5f * pw;
        py1 = pcy - 0.5f * ph;  py2 = pcy + 0.5f * ph;
        a1  = pw * ph;
        pconf = P[(size_t)base * 85 + 4];
        const float2 om = *reinterpret_cast<const float2*>(L + (size_t)base * 86 + 4); // 8B-aligned
        obj = om.x;  mix = om.y;
    }

    // ---- hot loop: iou >= 0.5  <=>  3*inter - barea >= a1  (w,h>=1 => union>=1) ----
    // two accumulators to break the FMNMX dependency chain
    float ma = -1e30f, mb = -1e30f;
    #pragma unroll 2
    for (int i = 0; i < NB; i += 2) {
        {
            const float4 bb = sb[i];
            float iw = fminf(px2, bb.z) - fmaxf(px1, bb.x);
            float ih = fminf(py2, bb.w) - fmaxf(py1, bb.y);
            iw = fmaxf(iw, 0.0f);  ih = fmaxf(ih, 0.0f);
            ma = fmaxf(ma, fmaf(3.0f, iw * ih, snb[i]));
        }
        {
            const float4 bb = sb[i + 1];
            float iw = fminf(px2, bb.z) - fmaxf(px1, bb.x);
            float ih = fminf(py2, bb.w) - fmaxf(py1, bb.y);
            iw = fmaxf(iw, 0.0f);  ih = fmaxf(ih, 0.0f);
            mb = fmaxf(mb, fmaf(3.0f, iw * ih, snb[i + 1]));
        }
    }
    const float m = fmaxf(ma, mb);

    // ---- per-anchor focal-conf / giou ----
    float lg = 0.0f, lc = 0.0f, lk = 0.0f;

    const float sig = 1.0f / (1.0f + __expf(-pconf));
    const float bce = softplus_f(pconf) - pconf * obj;
    const float d   = obj - sig;
    const float fl  = bce * d * d;

    float coef;
    if (obj > 0.0f) {
        coef = obj;
        // ---- GIoU vs label box (rare path) ----
        const float2 lxy = *reinterpret_cast<const float2*>(L + (size_t)base * 86);
        const float2 lwh = *reinterpret_cast<const float2*>(L + (size_t)base * 86 + 2);
        const float lx1 = lxy.x - 0.5f * lwh.x, lx2 = lxy.x + 0.5f * lwh.x;
        const float ly1 = lxy.y - 0.5f * lwh.y, ly2 = lxy.y + 0.5f * lwh.y;
        const float a2  = lwh.x * lwh.y;

        float iw = fminf(px2, lx2) - fmaxf(px1, lx1);
        float ih = fminf(py2, ly2) - fmaxf(py1, ly1);
        iw = fmaxf(iw, 0.0f);  ih = fmaxf(ih, 0.0f);
        const float inter = iw * ih;
        const float uni   = a1 + a2 - inter;
        const float iou   = inter / fmaxf(uni, EPSF);

        float ew = fmaxf(px2, lx2) - fminf(px1, lx1);
        float eh = fmaxf(py2, ly2) - fminf(py1, ly1);
        ew = fmaxf(ew, 0.0f);  eh = fmaxf(eh, 0.0f);
        const float ea   = ew * eh;
        const float giou = iou - (ea - uni) / fmaxf(ea, EPSF);

        lg = obj * (1.0f - giou) * mix;
    } else {
        coef = (m >= a1) ? 0.0f : 1.0f;   // noobj * (iou_max < 0.5)
    }
    lc = coef * fl * mix;                  // mix=0 for invalid anchors
    const float objmix = (valid && obj > 0.0f) ? obj * mix : 0.0f;

    // ---- cooperative class-BCE: whole warp serves each obj anchor ----
    const int lane = tid & 31;
    {
        unsigned mask = __ballot_sync(0xFFFFFFFFu, objmix > 0.0f);
        while (mask) {
            const int src = __ffs(mask) - 1;
            mask &= mask - 1;
            const int   sbase = __shfl_sync(0xFFFFFFFFu, base, src);
            const float w     = __shfl_sync(0xFFFFFFFFu, objmix, src);
            const float* Pc = P + (size_t)sbase * 85 + 5;
            const float* Lc = L + (size_t)sbase * 86 + 6;
            float s = 0.0f;
            #pragma unroll
            for (int c = lane; c < NC; c += 32) {
                const float xx = Pc[c];
                s += softplus_f(xx) - xx * Lc[c];
            }
            #pragma unroll
            for (int o = 16; o > 0; o >>= 1) s += __shfl_down_sync(0xFFFFFFFFu, s, o);
            if (lane == 0) lk += w * s;
        }
    }

    // ---- block reduction ----
    #pragma unroll
    for (int o = 16; o > 0; o >>= 1) {
        lg += __shfl_down_sync(0xFFFFFFFFu, lg, o);
        lc += __shfl_down_sync(0xFFFFFFFFu, lc, o);
        lk += __shfl_down_sync(0xFFFFFFFFu, lk, o);
    }
    __shared__ float rg[NT/32], rc[NT/32], rk[NT/32];
    __shared__ bool s_last;
    const int w = tid >> 5;
    if (lane == 0) { rg[w] = lg; rc[w] = lc; rk[w] = lk; }
    __syncthreads();

    if (tid == 0) {
        float sg = 0.0f, sc = 0.0f, sk = 0.0f;
        #pragma unroll
        for (int i = 0; i < NT/32; i++) { sg += rg[i]; sc += rc[i]; sk += rk[i]; }
        g_pg[bid] = (double)sg;
        g_pc[bid] = (double)sc;
        g_pk[bid] = (double)sk;
        __threadfence();
        const unsigned prev = atomicAdd(&g_count, 1u);
        s_last = (prev == GRID - 1);
    }
    __syncthreads();

    // ---- last block: reduce all partials, write outputs, reset counter ----
    if (s_last) {
        double dg = 0.0, dc = 0.0, dk = 0.0;
        for (int i = tid; i < GRID; i += NT) {
            dg += g_pg[i];  dc += g_pc[i];  dk += g_pk[i];
        }
        #pragma unroll
        for (int o = 16; o > 0; o >>= 1) {
            dg += __shfl_down_sync(0xFFFFFFFFu, dg, o);
            dc += __shfl_down_sync(0xFFFFFFFFu, dc, o);
            dk += __shfl_down_sync(0xFFFFFFFFu, dk, o);
        }
        __shared__ double zg[NT/32], zc[NT/32], zk[NT/32];
        if (lane == 0) { zg[w] = dg; zc[w] = dc; zk[w] = dk; }
        __syncthreads();
        if (tid == 0) {
            double fg = 0.0, fc = 0.0, fk = 0.0;
            #pragma unroll
            for (int i = 0; i < NT/32; i++) { fg += zg[i]; fc += zc[i]; fk += zk[i]; }
            const float og = (float)(fg / (double)BATCH);
            const float oc = (float)(fc / (double)BATCH);
            const float ok = (float)(fk / (double)BATCH);
            out[0] = og + oc + ok;
            out[1] = og;
            out[2] = oc;
            out[3] = ok;
            g_count = 0;           // restore state for next graph replay
        }
    }
}

extern "C" void kernel_launch(void* const* d_in, const int* in_sizes, int n_in,
                              void* d_out, int out_size)
{
    // harness order = dict insertion order of setup_inputs() (interleaved per scale):
    // 0: p_s   1: p_d_s  2: label_sbbox
    // 3: p_m   4: p_d_m  5: label_mbbox
    // 6: p_l   7: p_d_l  8: label_lbbox
    // 9: sbboxes  10: mbboxes  11: lbboxes
    fused_loss_kernel<<<GRID, NT>>>(
        (const float*)d_in[0], (const float*)d_in[1], (const float*)d_in[2],
        (const float*)d_in[3], (const float*)d_in[4], (const float*)d_in[5],
        (const float*)d_in[6], (const float*)d_in[7], (const float*)d_in[8],
        (const float*)d_in[9], (const float*)d_in[10], (const float*)d_in[11],
        (float*)d_out);
}